// round 13
// baseline (speedup 1.0000x reference)
#include <cuda_runtime.h>
#include <cuda_bf16.h>
#include <math.h>

// Problem constants
#define NN    4096
#define FF    128
#define HEADS 8
#define UU    8
#define CW    64           // HEADS*UU
#define BCOLS 80           // 64 M-cols, 8 expR cols, 1 ones col, 7 pad

// GEMM tiling
#define BM 64
#define BK 32
#define KSPLIT 8
#define KCHUNK (NN / KSPLIT)   // 512
#define NT (KCHUNK / BK)       // 16 tiles per CTA

// Scratch (no allocations allowed)
__device__ float          g_Wp[CW * FF];                 // W transposed [t][f]
__device__ __nv_bfloat16  g_Bh[(size_t)NN * BCOLS];      // B hi, n-major [node][80]
__device__ __nv_bfloat16  g_Bl[(size_t)NN * BCOLS];      // B lo
__device__ float          g_expEl[NN * HEADS];
__device__ float          g_Cp[(size_t)KSPLIT * NN * BCOLS];  // split-K partials

// ---------------------------------------------------------------------------
// Kernel 0: transpose W -> Wp[t][f], t = h*8+u
// ---------------------------------------------------------------------------
__global__ void wt_kernel(const float* __restrict__ W)
{
    int o = blockIdx.x * 256 + threadIdx.x;   // 0..8191
    int t = o >> 7, f = o & 127;
    g_Wp[o] = W[(t >> 3) * (FF * UU) + f * UU + (t & 7)];
}

// ---------------------------------------------------------------------------
// Kernel 1: prep. Warp-per-node: H row in regs, Wp in smem, butterfly reduce.
// Builds split-bf16 B (n-major): B[n][c], c<64: exp(e_r)*HW; 64+h: exp(e_r);
// 72: 1.0 (degree col); 73..79: 0.  Also exp(e_l) per (n,h).
// 256 blocks x 256 threads (8 warps), 2 nodes per warp.
// ---------------------------------------------------------------------------
__global__ __launch_bounds__(256) void prep_kernel(
    const float* __restrict__ H,
    const float* __restrict__ al_g, const float* __restrict__ ar_g)
{
    __shared__ float Ws[CW * FF];   // 32 KB, [t][f]

    int tid = threadIdx.x, lane = tid & 31, warp = tid >> 5;

    #pragma unroll
    for (int i = 0; i < 8; i++)
        ((float4*)Ws)[tid + i * 256] = ((const float4*)g_Wp)[tid + i * 256];

    float al0 = __ldg(al_g + lane),      ar0 = __ldg(ar_g + lane);
    float al1 = __ldg(al_g + 32 + lane), ar1 = __ldg(ar_g + 32 + lane);
    __syncthreads();

    #pragma unroll
    for (int rep = 0; rep < 2; rep++) {
        int n = blockIdx.x * 16 + warp * 2 + rep;
        float4 h4 = *(const float4*)&H[(size_t)n * FF + lane * 4];

        float hw0 = 0.f, hw1 = 0.f;
        #pragma unroll
        for (int t = 0; t < 64; t++) {
            float4 w4 = *(const float4*)&Ws[t * FF + lane * 4];
            float p = h4.x * w4.x + h4.y * w4.y + h4.z * w4.z + h4.w * w4.w;
            #pragma unroll
            for (int m = 16; m; m >>= 1)
                p += __shfl_xor_sync(0xffffffffu, p, m);
            if ((t & 31) == lane) { if (t < 32) hw0 = p; else hw1 = p; }
        }

        float el0 = hw0 * al0, er0 = hw0 * ar0;
        float el1 = hw1 * al1, er1 = hw1 * ar1;
        #pragma unroll
        for (int m = 1; m < 8; m <<= 1) {
            el0 += __shfl_xor_sync(0xffffffffu, el0, m);
            er0 += __shfl_xor_sync(0xffffffffu, er0, m);
            el1 += __shfl_xor_sync(0xffffffffu, el1, m);
            er1 += __shfl_xor_sync(0xffffffffu, er1, m);
        }
        float eR0 = expf(er0), eR1 = expf(er1);
        if ((lane & 7) == 0) {
            g_expEl[n * HEADS + (lane >> 3)]     = expf(el0);
            g_expEl[n * HEADS + 4 + (lane >> 3)] = expf(el1);
        }
        float v0 = hw0 * eR0, v1 = hw1 * eR1;
        __nv_bfloat16 b0 = __float2bfloat16(v0);
        __nv_bfloat16 b1 = __float2bfloat16(v1);
        g_Bh[(size_t)n * BCOLS + lane]      = b0;
        g_Bl[(size_t)n * BCOLS + lane]      = __float2bfloat16(v0 - __bfloat162float(b0));
        g_Bh[(size_t)n * BCOLS + 32 + lane] = b1;
        g_Bl[(size_t)n * BCOLS + 32 + lane] = __float2bfloat16(v1 - __bfloat162float(b1));

        // cols 64..79: head eRs, degree-1, pad zeros
        float eRlo = __shfl_sync(0xffffffffu, eR0, (lane & 3) * 8);
        float eRhi = __shfl_sync(0xffffffffu, eR1, (lane & 3) * 8);
        if (lane < 16) {
            float v2 = (lane < 4) ? eRlo
                     : (lane < 8) ? eRhi
                     : (lane == 8) ? 1.0f : 0.0f;
            __nv_bfloat16 b2 = __float2bfloat16(v2);
            g_Bh[(size_t)n * BCOLS + 64 + lane] = b2;
            g_Bl[(size_t)n * BCOLS + 64 + lane] =
                __float2bfloat16(v2 - __bfloat162float(b2));
        }
    }
}

// ---------------------------------------------------------------------------
// Kernel 2: pipelined split-K tensor-core GEMM. Cp[ks] = A @ (Bh + Bl).
// A fp32 (exact 0/1): LDG.cs 2 tiles ahead in regs -> cvt -> STS.
// B bf16: 3-stage cp.async ring. ldmatrix fragments.
// 256 threads = 8 warps (4 warp-rows x 16, 2 warp-cols x 40).
// ---------------------------------------------------------------------------
#define MMA16816(d, a, b0v, b1v)                                            \
    asm volatile(                                                           \
        "mma.sync.aligned.m16n8k16.row.col.f32.bf16.bf16.f32 "              \
        "{%0,%1,%2,%3}, {%4,%5,%6,%7}, {%8,%9}, {%0,%1,%2,%3};"             \
        : "+f"(d[0]), "+f"(d[1]), "+f"(d[2]), "+f"(d[3])                    \
        : "r"(a[0]), "r"(a[1]), "r"(a[2]), "r"(a[3]), "r"(b0v), "r"(b1v))

#define LDSM_X4(r0, r1, r2, r3, addr)                                       \
    asm volatile("ldmatrix.sync.aligned.m8n8.x4.shared.b16 "                \
                 "{%0,%1,%2,%3}, [%4];"                                     \
                 : "=r"(r0), "=r"(r1), "=r"(r2), "=r"(r3) : "r"(addr))

#define LDSM_X4T(r0, r1, r2, r3, addr)                                      \
    asm volatile("ldmatrix.sync.aligned.m8n8.x4.trans.shared.b16 "          \
                 "{%0,%1,%2,%3}, [%4];"                                     \
                 : "=r"(r0), "=r"(r1), "=r"(r2), "=r"(r3) : "r"(addr))

#define LDSM_X2T(r0, r1, addr)                                              \
    asm volatile("ldmatrix.sync.aligned.m8n8.x2.trans.shared.b16 "          \
                 "{%0,%1}, [%2];"                                           \
                 : "=r"(r0), "=r"(r1) : "r"(addr))

#define CP_ASYNC16(smaddr, gptr)                                            \
    asm volatile("cp.async.cg.shared.global [%0], [%1], 16;"                \
                 :: "r"(smaddr), "l"(gptr))

__global__ __launch_bounds__(256) void gemm_kernel(const float* __restrict__ A)
{
    __shared__ __nv_bfloat16 As[2][BM][40];     // 10 KB
    __shared__ __nv_bfloat16 Bhs[3][BK][88];    // 16.5 KB
    __shared__ __nv_bfloat16 Bls[3][BK][88];    // 16.5 KB

    int tid  = threadIdx.x;
    int lane = tid & 31;
    int warp = tid >> 5;
    int wr = warp & 3;          // rows wr*16..+15
    int wc = warp >> 2;         // cols wc*40..+39
    int row0 = blockIdx.x * BM;
    int k0   = blockIdx.y * KCHUNK;

    float acc[5][4];
    #pragma unroll
    for (int j = 0; j < 5; j++)
        #pragma unroll
        for (int q = 0; q < 4; q++) acc[j][q] = 0.f;

    // A: 64 rows x 32 k per tile; 4 threads per row, 8 floats (2 float4) each
    const float* aptr =
        A + (size_t)(row0 + (tid >> 2)) * NN + k0 + (tid & 3) * 8;

    float4 av[2][2];   // 2-tile-deep register prefetch

    // B issue: tile tt -> stage s. 640 16B chunks (hi+lo) over 256 threads.
    #define B_ISSUE(tt, s)                                                   \
        do {                                                                 \
            _Pragma("unroll")                                                \
            for (int i_ = 0; i_ < 3; i_++) {                                 \
                int c_ = tid + i_ * 256;                                     \
                if (c_ < 640) {                                              \
                    int mat_ = c_ >= 320;                                    \
                    int cc_  = mat_ ? c_ - 320 : c_;                         \
                    int kr_ = cc_ / 10, ch_ = cc_ % 10;                      \
                    const __nv_bfloat16* src_ = (mat_ ? g_Bl : g_Bh) +       \
                        (size_t)(k0 + (tt) * BK + kr_) * BCOLS + ch_ * 8;    \
                    unsigned d_ = (unsigned)__cvta_generic_to_shared(        \
                        mat_ ? &Bls[s][kr_][ch_ * 8]                         \
                             : &Bhs[s][kr_][ch_ * 8]);                       \
                    CP_ASYNC16(d_, src_);                                    \
                }                                                            \
            }                                                                \
        } while (0)

    // ---- prologue: B tiles 0,1 in flight; A tiles 0,1 in regs ----
    B_ISSUE(0, 0);
    asm volatile("cp.async.commit_group;");
    B_ISSUE(1, 1);
    asm volatile("cp.async.commit_group;");
    av[0][0] = __ldcs((const float4*)(aptr));
    av[0][1] = __ldcs((const float4*)(aptr + 4));
    av[1][0] = __ldcs((const float4*)(aptr + BK));
    av[1][1] = __ldcs((const float4*)(aptr + BK + 4));

    for (int kt = 0; kt < NT; kt++) {
        int abuf = kt & 1;
        int bst  = kt % 3;

        // STS A (convert fp32 -> bf16)
        {
            unsigned r8[8];
            #pragma unroll
            for (int q = 0; q < 2; q++) {
                __nv_bfloat162 p0 = __floats2bfloat162_rn(av[abuf][q].x, av[abuf][q].y);
                __nv_bfloat162 p1 = __floats2bfloat162_rn(av[abuf][q].z, av[abuf][q].w);
                r8[q * 2]     = *(unsigned*)&p0;
                r8[q * 2 + 1] = *(unsigned*)&p1;
            }
            __nv_bfloat16* dst = &As[abuf][tid >> 2][(tid & 3) * 8];
            *(uint4*)dst = make_uint4(r8[0], r8[1], r8[2], r8[3]);
        }
        // refill A regs for tile kt+2
        if (kt + 2 < NT) {
            av[abuf][0] = __ldcs((const float4*)(aptr + (kt + 2) * BK));
            av[abuf][1] = __ldcs((const float4*)(aptr + (kt + 2) * BK + 4));
        }
        // issue B for tile kt+2 (stage (kt+2)%3); one commit per iteration
        if (kt + 2 < NT) B_ISSUE(kt + 2, (kt + 2) % 3);
        asm volatile("cp.async.commit_group;");
        asm volatile("cp.async.wait_group 2;");
        __syncthreads();

        // ---- compute tile kt ----
        unsigned aBase = (unsigned)__cvta_generic_to_shared(&As[abuf][0][0]);
        #pragma unroll
        for (int kb = 0; kb < BK; kb += 16) {
            unsigned a[4];
            {
                int lr = lane & 15, lc = lane >> 4;
                unsigned ad = aBase + ((wr * 16 + lr) * 40 + kb + lc * 8) * 2;
                LDSM_X4(a[0], a[1], a[2], a[3], ad);
            }

            unsigned bh[5][2], bl[5][2];
            {
                int mm = lane >> 3;                       // 0..3
                int krow = kb + (mm & 1) * 8 + (lane & 7);
                #pragma unroll
                for (int jj = 0; jj < 2; jj++) {
                    int ncol = wc * 40 + jj * 16 + (mm >> 1) * 8;
                    unsigned adh = (unsigned)__cvta_generic_to_shared(
                        &Bhs[bst][krow][ncol]);
                    LDSM_X4T(bh[jj * 2][0], bh[jj * 2][1],
                             bh[jj * 2 + 1][0], bh[jj * 2 + 1][1], adh);
                    unsigned adl = (unsigned)__cvta_generic_to_shared(
                        &Bls[bst][krow][ncol]);
                    LDSM_X4T(bl[jj * 2][0], bl[jj * 2][1],
                             bl[jj * 2 + 1][0], bl[jj * 2 + 1][1], adl);
                }
                int krow2 = kb + ((lane >> 3) & 1) * 8 + (lane & 7);
                unsigned ad2h = (unsigned)__cvta_generic_to_shared(
                    &Bhs[bst][krow2][wc * 40 + 32]);
                LDSM_X2T(bh[4][0], bh[4][1], ad2h);
                unsigned ad2l = (unsigned)__cvta_generic_to_shared(
                    &Bls[bst][krow2][wc * 40 + 32]);
                LDSM_X2T(bl[4][0], bl[4][1], ad2l);
            }

            #pragma unroll
            for (int j = 0; j < 5; j++) {
                MMA16816(acc[j], a, bh[j][0], bh[j][1]);
                MMA16816(acc[j], a, bl[j][0], bl[j][1]);
            }
        }
        __syncthreads();
    }

    float* out = g_Cp + (size_t)blockIdx.y * NN * BCOLS;
    #pragma unroll
    for (int j = 0; j < 5; j++) {
        int r = row0 + wr * 16 + (lane >> 2);
        int c = wc * 40 + j * 8 + (lane & 3) * 2;
        out[(size_t)r * BCOLS + c]           = acc[j][0];
        out[(size_t)r * BCOLS + c + 1]       = acc[j][1];
        out[(size_t)(r + 8) * BCOLS + c]     = acc[j][2];
        out[(size_t)(r + 8) * BCOLS + c + 1] = acc[j][3];
    }
}

// ---------------------------------------------------------------------------
// Kernel 3: epilogue. Sum split-K partials, denom, scale, ELU, write.
//   denom[h,i] = (N - deg_i) + expEl[h,i] * S[h,i]
//   out[i, h*8+u] = elu(expEl[h,i] * T[h,i,u] / denom)
// ---------------------------------------------------------------------------
__global__ void epilogue_kernel(float* __restrict__ out)
{
    __shared__ float Crow[BCOLS];
    int i = blockIdx.x;
    int t = threadIdx.x;   // 80 threads

    float s = 0.f;
    #pragma unroll
    for (int ksp = 0; ksp < KSPLIT; ksp++)
        s += g_Cp[(size_t)ksp * NN * BCOLS + (size_t)i * BCOLS + t];
    Crow[t] = s;
    __syncthreads();

    if (t < CW) {
        int h = t >> 3;
        float T   = Crow[t];
        float S   = Crow[64 + h];
        float deg = Crow[72];
        float eEl = g_expEl[(size_t)i * HEADS + h];
        float denom = ((float)NN - deg) + eEl * S;
        float v = eEl * T / denom;
        out[(size_t)i * CW + t] = (v > 0.f) ? v : expm1f(v);
    }
}

// ---------------------------------------------------------------------------
extern "C" void kernel_launch(void* const* d_in, const int* in_sizes, int n_in,
                              void* d_out, int out_size)
{
    const float* A  = (const float*)d_in[0];   // [4096,4096]
    const float* H  = (const float*)d_in[1];   // [4096,128]
    const float* W  = (const float*)d_in[2];   // [8,128,8]
    const float* al = (const float*)d_in[3];   // [8,8]
    const float* ar = (const float*)d_in[4];   // [8,8]
    float* out = (float*)d_out;                // [4096,64]

    wt_kernel<<<32, 256>>>(W);
    prep_kernel<<<256, 256>>>(H, al, ar);
    gemm_kernel<<<dim3(NN / BM, KSPLIT), 256>>>(A);
    epilogue_kernel<<<NN, BCOLS>>>(out);
}

// round 14
// speedup vs baseline: 1.2115x; 1.2115x over previous
#include <cuda_runtime.h>
#include <cuda_bf16.h>
#include <math.h>

// Problem constants
#define NN    4096
#define FF    128
#define HEADS 8
#define UU    8
#define CW    64           // HEADS*UU
#define BCOLS 80           // 64 M-cols, 8 expR cols, 1 ones col, 7 pad

// GEMM tiling
#define BM 128
#define BK 32
#define KSPLIT 8
#define KCHUNK (NN / KSPLIT)   // 512
#define NT (KCHUNK / BK)       // 16 tiles per CTA

// Scratch (no allocations allowed)
__device__ float          g_Wp[CW * FF];                 // W transposed [t][f]
__device__ __nv_bfloat16  g_Bh[(size_t)NN * BCOLS];      // B hi, n-major [node][80]
__device__ __nv_bfloat16  g_Bl[(size_t)NN * BCOLS];      // B lo
__device__ float          g_expEl[NN * HEADS];
__device__ float          g_Cp[(size_t)KSPLIT * NN * BCOLS];  // split-K partials

// ---------------------------------------------------------------------------
// Kernel 0: transpose W -> Wp[t][f], t = h*8+u
// ---------------------------------------------------------------------------
__global__ void wt_kernel(const float* __restrict__ W)
{
    int o = blockIdx.x * 256 + threadIdx.x;   // 0..8191
    int t = o >> 7, f = o & 127;
    g_Wp[o] = W[(t >> 3) * (FF * UU) + f * UU + (t & 7)];
}

// ---------------------------------------------------------------------------
// Kernel 1: prep. Warp-per-node: H row in regs, Wp in smem, butterfly reduce.
// Builds split-bf16 B (n-major): B[n][c], c<64: exp(e_r)*HW; 64+h: exp(e_r);
// 72: 1.0 (degree col); 73..79: 0.  Also exp(e_l) per (n,h).
// 256 blocks x 256 threads (8 warps), 2 nodes per warp.
// ---------------------------------------------------------------------------
__global__ __launch_bounds__(256) void prep_kernel(
    const float* __restrict__ H,
    const float* __restrict__ al_g, const float* __restrict__ ar_g)
{
    __shared__ float Ws[CW * FF];   // 32 KB, [t][f]

    int tid = threadIdx.x, lane = tid & 31, warp = tid >> 5;

    #pragma unroll
    for (int i = 0; i < 8; i++)
        ((float4*)Ws)[tid + i * 256] = ((const float4*)g_Wp)[tid + i * 256];

    float al0 = __ldg(al_g + lane),      ar0 = __ldg(ar_g + lane);
    float al1 = __ldg(al_g + 32 + lane), ar1 = __ldg(ar_g + 32 + lane);
    __syncthreads();

    #pragma unroll
    for (int rep = 0; rep < 2; rep++) {
        int n = blockIdx.x * 16 + warp * 2 + rep;
        float4 h4 = *(const float4*)&H[(size_t)n * FF + lane * 4];

        float hw0 = 0.f, hw1 = 0.f;
        #pragma unroll
        for (int t = 0; t < 64; t++) {
            float4 w4 = *(const float4*)&Ws[t * FF + lane * 4];
            float p = h4.x * w4.x + h4.y * w4.y + h4.z * w4.z + h4.w * w4.w;
            #pragma unroll
            for (int m = 16; m; m >>= 1)
                p += __shfl_xor_sync(0xffffffffu, p, m);
            if ((t & 31) == lane) { if (t < 32) hw0 = p; else hw1 = p; }
        }

        float el0 = hw0 * al0, er0 = hw0 * ar0;
        float el1 = hw1 * al1, er1 = hw1 * ar1;
        #pragma unroll
        for (int m = 1; m < 8; m <<= 1) {
            el0 += __shfl_xor_sync(0xffffffffu, el0, m);
            er0 += __shfl_xor_sync(0xffffffffu, er0, m);
            el1 += __shfl_xor_sync(0xffffffffu, el1, m);
            er1 += __shfl_xor_sync(0xffffffffu, er1, m);
        }
        float eR0 = expf(er0), eR1 = expf(er1);
        if ((lane & 7) == 0) {
            g_expEl[n * HEADS + (lane >> 3)]     = expf(el0);
            g_expEl[n * HEADS + 4 + (lane >> 3)] = expf(el1);
        }
        float v0 = hw0 * eR0, v1 = hw1 * eR1;
        __nv_bfloat16 b0 = __float2bfloat16(v0);
        __nv_bfloat16 b1 = __float2bfloat16(v1);
        g_Bh[(size_t)n * BCOLS + lane]      = b0;
        g_Bl[(size_t)n * BCOLS + lane]      = __float2bfloat16(v0 - __bfloat162float(b0));
        g_Bh[(size_t)n * BCOLS + 32 + lane] = b1;
        g_Bl[(size_t)n * BCOLS + 32 + lane] = __float2bfloat16(v1 - __bfloat162float(b1));

        // cols 64..79: head eRs, degree-1, pad zeros
        float eRlo = __shfl_sync(0xffffffffu, eR0, (lane & 3) * 8);
        float eRhi = __shfl_sync(0xffffffffu, eR1, (lane & 3) * 8);
        if (lane < 16) {
            float v2 = (lane < 4) ? eRlo
                     : (lane < 8) ? eRhi
                     : (lane == 8) ? 1.0f : 0.0f;
            __nv_bfloat16 b2 = __float2bfloat16(v2);
            g_Bh[(size_t)n * BCOLS + 64 + lane] = b2;
            g_Bl[(size_t)n * BCOLS + 64 + lane] =
                __float2bfloat16(v2 - __bfloat162float(b2));
        }
    }
}

// ---------------------------------------------------------------------------
// Kernel 2: pipelined split-K tensor-core GEMM. Cp[ks] = A @ (Bh + Bl).
// BM=128, warp tile 32x40 (R8 shape). A fp32: LDG 1 tile ahead in regs.
// B bf16: 3-stage cp.async ring. ldmatrix fragments.
// Grid (32, 8) = 256 CTAs  ~= one wave at 2 CTAs/SM.
// ---------------------------------------------------------------------------
#define MMA16816(d, a, b0v, b1v)                                            \
    asm volatile(                                                           \
        "mma.sync.aligned.m16n8k16.row.col.f32.bf16.bf16.f32 "              \
        "{%0,%1,%2,%3}, {%4,%5,%6,%7}, {%8,%9}, {%0,%1,%2,%3};"             \
        : "+f"(d[0]), "+f"(d[1]), "+f"(d[2]), "+f"(d[3])                    \
        : "r"(a[0]), "r"(a[1]), "r"(a[2]), "r"(a[3]), "r"(b0v), "r"(b1v))

#define LDSM_X4(r0, r1, r2, r3, addr)                                       \
    asm volatile("ldmatrix.sync.aligned.m8n8.x4.shared.b16 "                \
                 "{%0,%1,%2,%3}, [%4];"                                     \
                 : "=r"(r0), "=r"(r1), "=r"(r2), "=r"(r3) : "r"(addr))

#define LDSM_X4T(r0, r1, r2, r3, addr)                                      \
    asm volatile("ldmatrix.sync.aligned.m8n8.x4.trans.shared.b16 "          \
                 "{%0,%1,%2,%3}, [%4];"                                     \
                 : "=r"(r0), "=r"(r1), "=r"(r2), "=r"(r3) : "r"(addr))

#define LDSM_X2T(r0, r1, addr)                                              \
    asm volatile("ldmatrix.sync.aligned.m8n8.x2.trans.shared.b16 "          \
                 "{%0,%1}, [%2];"                                           \
                 : "=r"(r0), "=r"(r1) : "r"(addr))

#define CP_ASYNC16(smaddr, gptr)                                            \
    asm volatile("cp.async.cg.shared.global [%0], [%1], 16;"                \
                 :: "r"(smaddr), "l"(gptr))

__global__ __launch_bounds__(256) void gemm_kernel(const float* __restrict__ A)
{
    __shared__ __nv_bfloat16 As[2][BM][40];     // 20 KB
    __shared__ __nv_bfloat16 Bhs[3][BK][88];    // 16.5 KB
    __shared__ __nv_bfloat16 Bls[3][BK][88];    // 16.5 KB

    int tid  = threadIdx.x;
    int lane = tid & 31;
    int warp = tid >> 5;
    int wr = warp & 3;          // rows wr*32..+31
    int wc = warp >> 2;         // cols wc*40..+39
    int row0 = blockIdx.x * BM;
    int k0   = blockIdx.y * KCHUNK;

    float acc[2][5][4];
    #pragma unroll
    for (int m = 0; m < 2; m++)
        #pragma unroll
        for (int j = 0; j < 5; j++)
            #pragma unroll
            for (int q = 0; q < 4; q++) acc[m][j][q] = 0.f;

    // A: 128 rows x 32 k per tile; 2 threads per row, 16 floats (4 float4)
    const float* aptr =
        A + (size_t)(row0 + (tid >> 1)) * NN + k0 + (tid & 1) * 16;

    float4 av[4];   // 1-tile register prefetch

    // B issue: tile tt -> stage s. 640 16B chunks (hi+lo) over 256 threads.
    #define B_ISSUE(tt, s)                                                   \
        do {                                                                 \
            _Pragma("unroll")                                                \
            for (int i_ = 0; i_ < 3; i_++) {                                 \
                int c_ = tid + i_ * 256;                                     \
                if (c_ < 640) {                                              \
                    int mat_ = c_ >= 320;                                    \
                    int cc_  = mat_ ? c_ - 320 : c_;                         \
                    int kr_ = cc_ / 10, ch_ = cc_ % 10;                      \
                    const __nv_bfloat16* src_ = (mat_ ? g_Bl : g_Bh) +       \
                        (size_t)(k0 + (tt) * BK + kr_) * BCOLS + ch_ * 8;    \
                    unsigned d_ = (unsigned)__cvta_generic_to_shared(        \
                        mat_ ? &Bls[s][kr_][ch_ * 8]                         \
                             : &Bhs[s][kr_][ch_ * 8]);                       \
                    CP_ASYNC16(d_, src_);                                    \
                }                                                            \
            }                                                                \
        } while (0)

    // ---- prologue: B tiles 0,1 in flight; A tile 0 in regs ----
    B_ISSUE(0, 0);
    asm volatile("cp.async.commit_group;");
    B_ISSUE(1, 1);
    asm volatile("cp.async.commit_group;");
    #pragma unroll
    for (int q = 0; q < 4; q++) av[q] = *(const float4*)(aptr + q * 4);

    for (int kt = 0; kt < NT; kt++) {
        int abuf = kt & 1;
        int bst  = kt % 3;

        // STS A (convert fp32 -> bf16)
        {
            unsigned r8[8];
            #pragma unroll
            for (int q = 0; q < 4; q++) {
                __nv_bfloat162 p0 = __floats2bfloat162_rn(av[q].x, av[q].y);
                __nv_bfloat162 p1 = __floats2bfloat162_rn(av[q].z, av[q].w);
                r8[q * 2]     = *(unsigned*)&p0;
                r8[q * 2 + 1] = *(unsigned*)&p1;
            }
            __nv_bfloat16* dst = &As[abuf][tid >> 1][(tid & 1) * 16];
            *(uint4*)dst       = make_uint4(r8[0], r8[1], r8[2], r8[3]);
            *(uint4*)(dst + 8) = make_uint4(r8[4], r8[5], r8[6], r8[7]);
        }
        // refill A regs for tile kt+1
        if (kt + 1 < NT) {
            #pragma unroll
            for (int q = 0; q < 4; q++)
                av[q] = *(const float4*)(aptr + (kt + 1) * BK + q * 4);
        }
        // issue B for tile kt+2 (stage (kt+2)%3); one commit per iteration
        if (kt + 2 < NT) B_ISSUE(kt + 2, (kt + 2) % 3);
        asm volatile("cp.async.commit_group;");
        asm volatile("cp.async.wait_group 2;");
        __syncthreads();

        // ---- compute tile kt ----
        unsigned aBase = (unsigned)__cvta_generic_to_shared(&As[abuf][0][0]);
        #pragma unroll
        for (int kb = 0; kb < BK; kb += 16) {
            unsigned a[2][4];
            int lr = lane & 15, lc = lane >> 4;
            #pragma unroll
            for (int m = 0; m < 2; m++) {
                unsigned ad = aBase +
                    ((wr * 32 + m * 16 + lr) * 40 + kb + lc * 8) * 2;
                LDSM_X4(a[m][0], a[m][1], a[m][2], a[m][3], ad);
            }

            unsigned bh[5][2], bl[5][2];
            {
                int mm = lane >> 3;                       // 0..3
                int krow = kb + (mm & 1) * 8 + (lane & 7);
                #pragma unroll
                for (int jj = 0; jj < 2; jj++) {
                    int ncol = wc * 40 + jj * 16 + (mm >> 1) * 8;
                    unsigned adh = (unsigned)__cvta_generic_to_shared(
                        &Bhs[bst][krow][ncol]);
                    LDSM_X4T(bh[jj * 2][0], bh[jj * 2][1],
                             bh[jj * 2 + 1][0], bh[jj * 2 + 1][1], adh);
                    unsigned adl = (unsigned)__cvta_generic_to_shared(
                        &Bls[bst][krow][ncol]);
                    LDSM_X4T(bl[jj * 2][0], bl[jj * 2][1],
                             bl[jj * 2 + 1][0], bl[jj * 2 + 1][1], adl);
                }
                int krow2 = kb + ((lane >> 3) & 1) * 8 + (lane & 7);
                unsigned ad2h = (unsigned)__cvta_generic_to_shared(
                    &Bhs[bst][krow2][wc * 40 + 32]);
                LDSM_X2T(bh[4][0], bh[4][1], ad2h);
                unsigned ad2l = (unsigned)__cvta_generic_to_shared(
                    &Bls[bst][krow2][wc * 40 + 32]);
                LDSM_X2T(bl[4][0], bl[4][1], ad2l);
            }

            #pragma unroll
            for (int j = 0; j < 5; j++)
                #pragma unroll
                for (int m = 0; m < 2; m++) {
                    MMA16816(acc[m][j], a[m], bh[j][0], bh[j][1]);
                    MMA16816(acc[m][j], a[m], bl[j][0], bl[j][1]);
                }
        }
        __syncthreads();
    }

    float* out = g_Cp + (size_t)blockIdx.y * NN * BCOLS;
    #pragma unroll
    for (int m = 0; m < 2; m++)
        #pragma unroll
        for (int j = 0; j < 5; j++) {
            int r = row0 + wr * 32 + m * 16 + (lane >> 2);
            int c = wc * 40 + j * 8 + (lane & 3) * 2;
            out[(size_t)r * BCOLS + c]           = acc[m][j][0];
            out[(size_t)r * BCOLS + c + 1]       = acc[m][j][1];
            out[(size_t)(r + 8) * BCOLS + c]     = acc[m][j][2];
            out[(size_t)(r + 8) * BCOLS + c + 1] = acc[m][j][3];
        }
}

// ---------------------------------------------------------------------------
// Kernel 3: epilogue. Sum split-K partials, denom, scale, ELU, write.
//   denom[h,i] = (N - deg_i) + expEl[h,i] * S[h,i]
//   out[i, h*8+u] = elu(expEl[h,i] * T[h,i,u] / denom)
// 1024 blocks x 320 threads; block handles 4 rows (4 x 80 cols),
// 8 independent strided loads per thread (full MLP).
// ---------------------------------------------------------------------------
__global__ __launch_bounds__(320) void epilogue_kernel(float* __restrict__ out)
{
    __shared__ float Crow[4][BCOLS];
    int t  = threadIdx.x;          // 0..319
    int lr = t / BCOLS;            // 0..3
    int c  = t - lr * BCOLS;       // 0..79
    int i  = blockIdx.x * 4 + lr;  // node row

    float s0 = 0.f, s1 = 0.f;
    size_t base = (size_t)i * BCOLS + c;
    #pragma unroll
    for (int ksp = 0; ksp < KSPLIT; ksp += 2) {
        s0 += g_Cp[(size_t)ksp * NN * BCOLS + base];
        s1 += g_Cp[(size_t)(ksp + 1) * NN * BCOLS + base];
    }
    Crow[lr][c] = s0 + s1;
    __syncthreads();

    if (c < CW) {
        int h = c >> 3;
        float T   = Crow[lr][c];
        float S   = Crow[lr][64 + h];
        float deg = Crow[lr][72];
        float eEl = g_expEl[(size_t)i * HEADS + h];
        float denom = ((float)NN - deg) + eEl * S;
        float v = eEl * T / denom;
        out[(size_t)i * CW + c] = (v > 0.f) ? v : expm1f(v);
    }
}

// ---------------------------------------------------------------------------
extern "C" void kernel_launch(void* const* d_in, const int* in_sizes, int n_in,
                              void* d_out, int out_size)
{
    const float* A  = (const float*)d_in[0];   // [4096,4096]
    const float* H  = (const float*)d_in[1];   // [4096,128]
    const float* W  = (const float*)d_in[2];   // [8,128,8]
    const float* al = (const float*)d_in[3];   // [8,8]
    const float* ar = (const float*)d_in[4];   // [8,8]
    float* out = (float*)d_out;                // [4096,64]

    wt_kernel<<<32, 256>>>(W);
    prep_kernel<<<256, 256>>>(H, al, ar);
    gemm_kernel<<<dim3(NN / BM, KSPLIT), 256>>>(A);
    epilogue_kernel<<<NN / 4, 320>>>(out);
}